// round 1
// baseline (speedup 1.0000x reference)
#include <cuda_runtime.h>
#include <math_constants.h>

#define B_  4
#define H_  16
#define S_  2048
#define DM  1024
#define DK  64
#define M_  (B_*S_)

// Scratch (device globals — no allocation allowed)
__device__ float g_Q[M_*DM];
__device__ float g_K[M_*DM];
__device__ float g_V[M_*DM];
__device__ float g_attn[M_*DM];

typedef unsigned long long ull;

__device__ __forceinline__ ull pk2(float x, float y) {
    ull r;
    asm("mov.b64 %0, {%1, %2};" : "=l"(r)
        : "r"(__float_as_uint(x)), "r"(__float_as_uint(y)));
    return r;
}
__device__ __forceinline__ float2 upk2(ull v) {
    unsigned a, b;
    asm("mov.b64 {%0, %1}, %2;" : "=r"(a), "=r"(b) : "l"(v));
    return make_float2(__uint_as_float(a), __uint_as_float(b));
}
// Packed dual-FMA (Blackwell f32x2) — 2 fp32 FMAs per instruction
__device__ __forceinline__ ull fma2(ull a, ull b, ull c) {
    ull d;
    asm("fma.rn.f32x2 %0, %1, %2, %3;" : "=l"(d) : "l"(a), "l"(b), "l"(c));
    return d;
}

// ---------------------------------------------------------------------------
// GEMM: out[m,n] = sum_k A[m,k] * W[n,k] + bias[n]
// A: [8192,1024] row-major, W: [1024,1024] row-major (both K-contiguous, "NT")
// split_heads=1: write to [B,H,S,Dk] layout. split_heads=0: plain [M,N].
// Tile: BM=128, BN=64, BK=16; 256 threads; each thread 8x4 outputs, f32x2 acc.
// ---------------------------------------------------------------------------
__global__ __launch_bounds__(256, 2)
void gemm_nt_kernel(const float* __restrict__ A, const float* __restrict__ W,
                    const float* __restrict__ bias, float* __restrict__ out,
                    int split_heads)
{
    __shared__ float As[16][132];   // [k][m], padded (bank-friendly, 16B-aligned rows)
    __shared__ float Bs[16][68];    // [k][n]

    const int tid = threadIdx.x;
    const int ty  = tid >> 4;       // 0..15 -> 8 rows each
    const int tx  = tid & 15;       // 0..15 -> 4 cols each
    const int m0  = blockIdx.y << 7;
    const int n0  = blockIdx.x << 6;

    ull acc[4][4];                  // 4 row-pairs x 4 cols, packed f32x2
    #pragma unroll
    for (int p = 0; p < 4; p++)
        #pragma unroll
        for (int j = 0; j < 4; j++) acc[p][j] = 0ULL;

    const int lrow = tid >> 2;              // 0..63
    const int lk   = (tid & 3) << 2;        // 0,4,8,12
    const float* Ap0 = A + (size_t)(m0 + lrow) * DM + lk;
    const float* Ap1 = Ap0 + (size_t)64 * DM;
    const float* Wp  = W + (size_t)(n0 + lrow) * DM + lk;

    for (int k0 = 0; k0 < DM; k0 += 16) {
        float4 a0 = *(const float4*)(Ap0 + k0);
        float4 a1 = *(const float4*)(Ap1 + k0);
        float4 b0 = *(const float4*)(Wp + k0);
        __syncthreads();
        As[lk+0][lrow]    = a0.x; As[lk+1][lrow]    = a0.y;
        As[lk+2][lrow]    = a0.z; As[lk+3][lrow]    = a0.w;
        As[lk+0][lrow+64] = a1.x; As[lk+1][lrow+64] = a1.y;
        As[lk+2][lrow+64] = a1.z; As[lk+3][lrow+64] = a1.w;
        Bs[lk+0][lrow] = b0.x; Bs[lk+1][lrow] = b0.y;
        Bs[lk+2][lrow] = b0.z; Bs[lk+3][lrow] = b0.w;
        __syncthreads();
        #pragma unroll
        for (int kk = 0; kk < 16; kk++) {
            ulonglong2 av0 = *(const ulonglong2*)&As[kk][ty << 3];
            ulonglong2 av1 = *(const ulonglong2*)&As[kk][(ty << 3) + 4];
            float4 bv = *(const float4*)&Bs[kk][tx << 2];
            ull bd0 = pk2(bv.x, bv.x);
            ull bd1 = pk2(bv.y, bv.y);
            ull bd2 = pk2(bv.z, bv.z);
            ull bd3 = pk2(bv.w, bv.w);
            acc[0][0] = fma2(av0.x, bd0, acc[0][0]);
            acc[0][1] = fma2(av0.x, bd1, acc[0][1]);
            acc[0][2] = fma2(av0.x, bd2, acc[0][2]);
            acc[0][3] = fma2(av0.x, bd3, acc[0][3]);
            acc[1][0] = fma2(av0.y, bd0, acc[1][0]);
            acc[1][1] = fma2(av0.y, bd1, acc[1][1]);
            acc[1][2] = fma2(av0.y, bd2, acc[1][2]);
            acc[1][3] = fma2(av0.y, bd3, acc[1][3]);
            acc[2][0] = fma2(av1.x, bd0, acc[2][0]);
            acc[2][1] = fma2(av1.x, bd1, acc[2][1]);
            acc[2][2] = fma2(av1.x, bd2, acc[2][2]);
            acc[2][3] = fma2(av1.x, bd3, acc[2][3]);
            acc[3][0] = fma2(av1.y, bd0, acc[3][0]);
            acc[3][1] = fma2(av1.y, bd1, acc[3][1]);
            acc[3][2] = fma2(av1.y, bd2, acc[3][2]);
            acc[3][3] = fma2(av1.y, bd3, acc[3][3]);
        }
    }

    float4 bb = *(const float4*)(bias + n0 + (tx << 2));
    #pragma unroll
    for (int p = 0; p < 4; p++) {
        float2 c0 = upk2(acc[p][0]);
        float2 c1 = upk2(acc[p][1]);
        float2 c2 = upk2(acc[p][2]);
        float2 c3 = upk2(acc[p][3]);
        int r0 = m0 + (ty << 3) + (p << 1);   // even row; r0+1 same (b, head-row)
        float4 o0 = make_float4(c0.x + bb.x, c1.x + bb.y, c2.x + bb.z, c3.x + bb.w);
        float4 o1 = make_float4(c0.y + bb.x, c1.y + bb.y, c2.y + bb.z, c3.y + bb.w);
        if (split_heads) {
            int h  = n0 >> 6;                 // BN == DK: one head per block col
            int bi = r0 >> 11;
            int si = r0 & (S_ - 1);
            size_t idx = ((size_t)(bi * H_ + h) * S_ + si) * DK + (tx << 2);
            *(float4*)(out + idx)      = o0;
            *(float4*)(out + idx + DK) = o1;  // si+1, same batch (r0 even)
        } else {
            size_t idx = (size_t)r0 * DM + n0 + (tx << 2);
            *(float4*)(out + idx)      = o0;
            *(float4*)(out + idx + DM) = o1;
        }
    }
}

// ---------------------------------------------------------------------------
// Flash attention: per (b, h, 64-row q-tile); K/V in 32-row tiles.
// Output written to merged-head layout [B, S, H*Dk] for the final projection.
// Static smem = 44 KB. Thread (ty,tx): 4 q-rows x (2 score cols / 4 dk cols).
// ---------------------------------------------------------------------------
__global__ __launch_bounds__(256, 2)
void attn_kernel(const float* __restrict__ Qh, const float* __restrict__ Kh,
                 const float* __restrict__ Vh, float* __restrict__ outA)
{
    __shared__ float Qs[64][68];   // [d][q]
    __shared__ float Ks[64][36];   // [d][k]
    __shared__ float Vs[32][68];   // [k][d]
    __shared__ float Ps[32][68];   // [k][q]  (transposed probs)

    const int tid = threadIdx.x;
    const int ty  = tid >> 4;      // 0..15 -> q rows ty*4..ty*4+3
    const int tx  = tid & 15;      // 0..15 -> score cols tx*2, dk cols tx*4
    const int qt  = blockIdx.x;
    const int h   = blockIdx.y;
    const int b   = blockIdx.z;

    const size_t bh = (size_t)(b * H_ + h) * S_ * DK;
    const float* Qb = Qh + bh + (size_t)qt * 64 * DK;
    const float* Kb = Kh + bh;
    const float* Vb = Vh + bh;

    // Load Q tile transposed [d][q]
    {
        int q = tid >> 2;
        int dbase = (tid & 3) << 2;
        #pragma unroll
        for (int c = 0; c < 4; c++) {
            int d = dbase + (c << 4);
            float4 v = *(const float4*)(Qb + q * DK + d);
            Qs[d+0][q] = v.x; Qs[d+1][q] = v.y; Qs[d+2][q] = v.z; Qs[d+3][q] = v.w;
        }
    }

    float m_i[4], l_i[4], o[4][4];
    #pragma unroll
    for (int i = 0; i < 4; i++) {
        m_i[i] = -CUDART_INF_F;
        l_i[i] = 0.f;
        #pragma unroll
        for (int j = 0; j < 4; j++) o[i][j] = 0.f;
    }

    const int kr = tid >> 3;            // 0..31
    const int d8 = (tid & 7) << 3;      // 0..56 step 8

    for (int k0 = 0; k0 < S_; k0 += 32) {
        const float* kp = Kb + (size_t)(k0 + kr) * DK + d8;
        const float* vp = Vb + (size_t)(k0 + kr) * DK + d8;
        float4 kv0 = *(const float4*)(kp);
        float4 kv1 = *(const float4*)(kp + 4);
        float4 vv0 = *(const float4*)(vp);
        float4 vv1 = *(const float4*)(vp + 4);
        __syncthreads();   // previous iteration's Ks/Vs/Ps consumers done
        Ks[d8+0][kr] = kv0.x; Ks[d8+1][kr] = kv0.y;
        Ks[d8+2][kr] = kv0.z; Ks[d8+3][kr] = kv0.w;
        Ks[d8+4][kr] = kv1.x; Ks[d8+5][kr] = kv1.y;
        Ks[d8+6][kr] = kv1.z; Ks[d8+7][kr] = kv1.w;
        *(float4*)&Vs[kr][d8]     = vv0;
        *(float4*)&Vs[kr][d8 + 4] = vv1;
        __syncthreads();

        // S tile: 4 rows x 2 cols per thread
        float s[4][2];
        #pragma unroll
        for (int i = 0; i < 4; i++) { s[i][0] = 0.f; s[i][1] = 0.f; }
        #pragma unroll 16
        for (int d = 0; d < 64; d++) {
            float4 qv = *(const float4*)&Qs[d][ty << 2];
            float2 kv = *(const float2*)&Ks[d][tx << 1];
            s[0][0] += qv.x * kv.x; s[0][1] += qv.x * kv.y;
            s[1][0] += qv.y * kv.x; s[1][1] += qv.y * kv.y;
            s[2][0] += qv.z * kv.x; s[2][1] += qv.z * kv.y;
            s[3][0] += qv.w * kv.x; s[3][1] += qv.w * kv.y;
        }

        // Online softmax (row reduce across the 16 tx lanes)
        #pragma unroll
        for (int i = 0; i < 4; i++) {
            float a0 = s[i][0] * 0.125f;    // 1/sqrt(64)
            float a1 = s[i][1] * 0.125f;
            float rm = fmaxf(a0, a1);
            #pragma unroll
            for (int msk = 1; msk < 16; msk <<= 1)
                rm = fmaxf(rm, __shfl_xor_sync(0xffffffffu, rm, msk));
            float mnew  = fmaxf(m_i[i], rm);
            float p0    = __expf(a0 - mnew);
            float p1    = __expf(a1 - mnew);
            float alpha = __expf(m_i[i] - mnew);
            m_i[i] = mnew;
            float rs = p0 + p1;
            #pragma unroll
            for (int msk = 1; msk < 16; msk <<= 1)
                rs += __shfl_xor_sync(0xffffffffu, rs, msk);
            l_i[i] = l_i[i] * alpha + rs;
            o[i][0] *= alpha; o[i][1] *= alpha; o[i][2] *= alpha; o[i][3] *= alpha;
            Ps[(tx << 1) + 0][(ty << 2) + i] = p0;
            Ps[(tx << 1) + 1][(ty << 2) + i] = p1;
        }
        __syncthreads();

        // O += P * V : 4 rows x 4 dk cols per thread
        #pragma unroll 8
        for (int kk = 0; kk < 32; kk++) {
            float4 pv = *(const float4*)&Ps[kk][ty << 2];
            float4 vv = *(const float4*)&Vs[kk][tx << 2];
            o[0][0] += pv.x * vv.x; o[0][1] += pv.x * vv.y;
            o[0][2] += pv.x * vv.z; o[0][3] += pv.x * vv.w;
            o[1][0] += pv.y * vv.x; o[1][1] += pv.y * vv.y;
            o[1][2] += pv.y * vv.z; o[1][3] += pv.y * vv.w;
            o[2][0] += pv.z * vv.x; o[2][1] += pv.z * vv.y;
            o[2][2] += pv.z * vv.z; o[2][3] += pv.z * vv.w;
            o[3][0] += pv.w * vv.x; o[3][1] += pv.w * vv.y;
            o[3][2] += pv.w * vv.z; o[3][3] += pv.w * vv.w;
        }
    }

    // Normalize and store to [B, S, H*Dk]
    #pragma unroll
    for (int i = 0; i < 4; i++) {
        float inv = 1.0f / l_i[i];
        float4 ov = make_float4(o[i][0] * inv, o[i][1] * inv,
                                o[i][2] * inv, o[i][3] * inv);
        int q = qt * 64 + (ty << 2) + i;
        size_t idx = ((size_t)(b * S_ + q)) * DM + h * DK + (tx << 2);
        *(float4*)(outA + idx) = ov;
    }
}

// ---------------------------------------------------------------------------
extern "C" void kernel_launch(void* const* d_in, const int* in_sizes, int n_in,
                              void* d_out, int out_size)
{
    const float* q  = (const float*)d_in[0];
    const float* k  = (const float*)d_in[1];
    const float* v  = (const float*)d_in[2];
    const float* Wq = (const float*)d_in[3];
    const float* bq = (const float*)d_in[4];
    const float* Wk = (const float*)d_in[5];
    const float* bk = (const float*)d_in[6];
    const float* Wv = (const float*)d_in[7];
    const float* bv = (const float*)d_in[8];
    const float* Wo = (const float*)d_in[9];
    const float* bo = (const float*)d_in[10];
    float* out = (float*)d_out;

    float *gQ, *gK, *gV, *gA;
    cudaGetSymbolAddress((void**)&gQ, g_Q);
    cudaGetSymbolAddress((void**)&gK, g_K);
    cudaGetSymbolAddress((void**)&gV, g_V);
    cudaGetSymbolAddress((void**)&gA, g_attn);

    dim3 gg(DM / 64, M_ / 128);   // (16, 64)
    gemm_nt_kernel<<<gg, 256>>>(q, Wq, bq, gQ, 1);
    gemm_nt_kernel<<<gg, 256>>>(k, Wk, bk, gK, 1);
    gemm_nt_kernel<<<gg, 256>>>(v, Wv, bv, gV, 1);
    attn_kernel<<<dim3(S_ / 64, H_, B_), 256>>>(gQ, gK, gV, gA);
    gemm_nt_kernel<<<gg, 256>>>(gA, Wo, bo, out, 0);
}

// round 3
// speedup vs baseline: 1.2282x; 1.2282x over previous
#include <cuda_runtime.h>
#include <cuda_bf16.h>
#include <math_constants.h>
#include <cstdint>

#define B_  4
#define H_  16
#define S_  2048
#define DM  1024
#define DK  64
#define M_  (B_*S_)

// ---------------- scratch (device globals; no allocation allowed) ----------
__device__ float g_Q[M_*DM];
__device__ float g_K[M_*DM];
__device__ float g_V[M_*DM];
__device__ float g_attn[M_*DM];

__device__ __forceinline__ uint32_t smem_u32(const void* p) {
    uint32_t a;
    asm("{ .reg .u64 t; cvta.to.shared.u64 t, %1; cvt.u32.u64 %0, t; }"
        : "=r"(a) : "l"(p));
    return a;
}

__device__ __forceinline__ void ldsm_x4(uint32_t r[4], uint32_t addr) {
    asm volatile("ldmatrix.sync.aligned.m8n8.x4.shared.b16 {%0,%1,%2,%3}, [%4];"
        : "=r"(r[0]), "=r"(r[1]), "=r"(r[2]), "=r"(r[3]) : "r"(addr));
}
__device__ __forceinline__ void ldsm_x2(uint32_t r[2], uint32_t addr) {
    asm volatile("ldmatrix.sync.aligned.m8n8.x2.shared.b16 {%0,%1}, [%2];"
        : "=r"(r[0]), "=r"(r[1]) : "r"(addr));
}
__device__ __forceinline__ void mma16816(float d[4], const uint32_t a[4],
                                         const uint32_t b[2]) {
    asm volatile(
        "mma.sync.aligned.m16n8k16.row.col.f32.bf16.bf16.f32 "
        "{%0,%1,%2,%3}, {%4,%5,%6,%7}, {%8,%9}, {%0,%1,%2,%3};"
        : "+f"(d[0]), "+f"(d[1]), "+f"(d[2]), "+f"(d[3])
        : "r"(a[0]), "r"(a[1]), "r"(a[2]), "r"(a[3]), "r"(b[0]), "r"(b[1]));
}

__device__ __forceinline__ uint32_t pk_bf2(float x, float y) {
    __nv_bfloat162 h = __floats2bfloat162_rn(x, y);
    return *reinterpret_cast<uint32_t*>(&h);
}

// Split 8 fp32 (two float4) into hi/lo bf16x8 (uint4 each)
__device__ __forceinline__ void split8(float4 v0, float4 v1,
                                       uint4& hi, uint4& lo) {
    float h[8], f[8] = {v0.x, v0.y, v0.z, v0.w, v1.x, v1.y, v1.z, v1.w};
    float l[8];
    #pragma unroll
    for (int i = 0; i < 8; i++) {
        __nv_bfloat16 hb = __float2bfloat16_rn(f[i]);
        h[i] = __bfloat162float(hb);
        l[i] = f[i] - h[i];
    }
    hi = make_uint4(pk_bf2(h[0],h[1]), pk_bf2(h[2],h[3]),
                    pk_bf2(h[4],h[5]), pk_bf2(h[6],h[7]));
    lo = make_uint4(pk_bf2(l[0],l[1]), pk_bf2(l[2],l[3]),
                    pk_bf2(l[4],l[5]), pk_bf2(l[6],l[7]));
}

// ---------------------------------------------------------------------------
// Tensor-core GEMM via mma.sync (HMMA, no 'a'-gated features):
//   out[m,n] = sum_k A[m,k]*W[n,k] + bias[n]
// fp32 emulated as Ahi*Whi + Alo*Whi + Ahi*Wlo (split fused into tile loader).
// CTA tile 128x128, BK=32, 8 warps (2x4), warp tile 64x32.
// smem tiles: bf16 [128][32] stored with 80-byte row stride (conflict-free
// for ldmatrix: 80 mod 128 cycles through all 8 16B positions).
// ---------------------------------------------------------------------------
#define TSTR   80
#define TILEB  (128*TSTR)     // 10240 B
#define A_HI   0
#define A_LO   TILEB
#define W_HI   (2*TILEB)
#define W_LO   (3*TILEB)

__global__ __launch_bounds__(256)
void gemm_mma(const float* __restrict__ A, const float* __restrict__ W,
              const float* __restrict__ bias, float* __restrict__ out,
              int split_heads)
{
    __shared__ __align__(16) char sm[4*TILEB];   // 40 KB
    const uint32_t sb = smem_u32(sm);

    const int tid = threadIdx.x;
    const int m0  = blockIdx.y << 7;
    const int n0  = blockIdx.x << 7;
    const int warp = tid >> 5;
    const int lane = tid & 31;
    const int wm = (warp >> 2) * 64;     // warp m offset (0/64)
    const int wn = (warp & 3) * 32;      // warp n offset (0..96)

    // ldmatrix per-lane row offsets (bytes)
    const uint32_t arow = (lane & 15) * TSTR + (lane >> 4) * 16;
    const uint32_t brow = (lane & 7) * TSTR + ((lane >> 3) & 1) * 16;

    // loader mapping: thread -> (row, 16-float column group)
    const int lrow = tid >> 1;
    const int lcg  = (tid & 1) * 16;
    const float* Ag = A + (size_t)(m0 + lrow) * DM + lcg;
    const float* Wg = W + (size_t)(n0 + lrow) * DM + lcg;
    char* smArow = sm + lrow * TSTR + lcg * 2;
    char* smWrow = smArow;   // same offsets, different tile bases

    float acc[4][4][4];
    #pragma unroll
    for (int i = 0; i < 4; i++)
        #pragma unroll
        for (int j = 0; j < 4; j++)
            #pragma unroll
            for (int r = 0; r < 4; r++) acc[i][j][r] = 0.f;

    // prologue: load chunk 0
    float4 ra0 = *(const float4*)(Ag);      float4 ra1 = *(const float4*)(Ag + 4);
    float4 ra2 = *(const float4*)(Ag + 8);  float4 ra3 = *(const float4*)(Ag + 12);
    float4 rw0 = *(const float4*)(Wg);      float4 rw1 = *(const float4*)(Wg + 4);
    float4 rw2 = *(const float4*)(Wg + 8);  float4 rw3 = *(const float4*)(Wg + 12);

    for (int c = 0; c < DM / 32; ++c) {
        __syncthreads();   // previous compute done before smem overwrite
        uint4 hi, lo;
        split8(ra0, ra1, hi, lo);
        *(uint4*)(smArow + A_HI)      = hi;  *(uint4*)(smArow + A_LO)      = lo;
        split8(ra2, ra3, hi, lo);
        *(uint4*)(smArow + A_HI + 16) = hi;  *(uint4*)(smArow + A_LO + 16) = lo;
        split8(rw0, rw1, hi, lo);
        *(uint4*)(smWrow + W_HI)      = hi;  *(uint4*)(smWrow + W_LO)      = lo;
        split8(rw2, rw3, hi, lo);
        *(uint4*)(smWrow + W_HI + 16) = hi;  *(uint4*)(smWrow + W_LO + 16) = lo;
        __syncthreads();

        if (c < DM / 32 - 1) {           // prefetch next chunk into regs
            const float* An = Ag + (c + 1) * 32;
            const float* Wn = Wg + (c + 1) * 32;
            ra0 = *(const float4*)(An);      ra1 = *(const float4*)(An + 4);
            ra2 = *(const float4*)(An + 8);  ra3 = *(const float4*)(An + 12);
            rw0 = *(const float4*)(Wn);      rw1 = *(const float4*)(Wn + 4);
            rw2 = *(const float4*)(Wn + 8);  rw3 = *(const float4*)(Wn + 12);
        }

        // 3 passes: (Ahi,Whi), (Alo,Whi), (Ahi,Wlo)
        #pragma unroll
        for (int pass = 0; pass < 3; ++pass) {
            const uint32_t aoff = (pass == 1) ? A_LO : A_HI;
            const uint32_t boff = (pass == 2) ? W_LO : W_HI;
            #pragma unroll
            for (int ks = 0; ks < 2; ++ks) {
                uint32_t af[4][4], bf[4][2];
                #pragma unroll
                for (int mt = 0; mt < 4; ++mt)
                    ldsm_x4(af[mt], sb + aoff + (wm + mt*16) * TSTR
                                        + ks * 32 + arow);
                #pragma unroll
                for (int nt = 0; nt < 4; ++nt)
                    ldsm_x2(bf[nt], sb + boff + (wn + nt*8) * TSTR
                                        + ks * 32 + brow);
                #pragma unroll
                for (int mt = 0; mt < 4; ++mt)
                    #pragma unroll
                    for (int nt = 0; nt < 4; ++nt)
                        mma16816(acc[mt][nt], af[mt], bf[nt]);
            }
        }
    }

    // Epilogue: c-fragment layout: (row=l/4 [+8], col=2*(l%4)+{0,1})
    #pragma unroll
    for (int mt = 0; mt < 4; ++mt) {
        #pragma unroll
        for (int nt = 0; nt < 4; ++nt) {
            const int col = n0 + wn + nt*8 + (lane & 3) * 2;
            const float2 bv = *(const float2*)(bias + col);
            #pragma unroll
            for (int half = 0; half < 2; ++half) {
                const int row = m0 + wm + mt*16 + (lane >> 2) + half * 8;
                float2 o2 = make_float2(acc[mt][nt][2*half]   + bv.x,
                                        acc[mt][nt][2*half+1] + bv.y);
                size_t idx;
                if (split_heads) {
                    const int head = col >> 6;
                    const int bi = row >> 11, si = row & (S_ - 1);
                    idx = (((size_t)(bi * H_ + head)) * S_ + si) * DK + (col & 63);
                } else {
                    idx = (size_t)row * DM + col;
                }
                *(float2*)(out + idx) = o2;
            }
        }
    }
}

// ---------------------------------------------------------------------------
// Flash attention (unchanged R1): per (b, h, 64-row q-tile); K/V 32-row tiles.
// ---------------------------------------------------------------------------
__global__ __launch_bounds__(256, 2)
void attn_kernel(const float* __restrict__ Qh, const float* __restrict__ Kh,
                 const float* __restrict__ Vh, float* __restrict__ outA)
{
    __shared__ float Qs[64][68];
    __shared__ float Ks[64][36];
    __shared__ float Vs[32][68];
    __shared__ float Ps[32][68];

    const int tid = threadIdx.x;
    const int ty  = tid >> 4;
    const int tx  = tid & 15;
    const int qt  = blockIdx.x;
    const int h   = blockIdx.y;
    const int b   = blockIdx.z;

    const size_t bh = (size_t)(b * H_ + h) * S_ * DK;
    const float* Qb = Qh + bh + (size_t)qt * 64 * DK;
    const float* Kb = Kh + bh;
    const float* Vb = Vh + bh;

    {
        int q = tid >> 2;
        int dbase = (tid & 3) << 2;
        #pragma unroll
        for (int c = 0; c < 4; c++) {
            int d = dbase + (c << 4);
            float4 v = *(const float4*)(Qb + q * DK + d);
            Qs[d+0][q] = v.x; Qs[d+1][q] = v.y; Qs[d+2][q] = v.z; Qs[d+3][q] = v.w;
        }
    }

    float m_i[4], l_i[4], o[4][4];
    #pragma unroll
    for (int i = 0; i < 4; i++) {
        m_i[i] = -CUDART_INF_F;
        l_i[i] = 0.f;
        #pragma unroll
        for (int j = 0; j < 4; j++) o[i][j] = 0.f;
    }

    const int kr = tid >> 3;
    const int d8 = (tid & 7) << 3;

    for (int k0 = 0; k0 < S_; k0 += 32) {
        const float* kp = Kb + (size_t)(k0 + kr) * DK + d8;
        const float* vp = Vb + (size_t)(k0 + kr) * DK + d8;
        float4 kv0 = *(const float4*)(kp);
        float4 kv1 = *(const float4*)(kp + 4);
        float4 vv0 = *(const float4*)(vp);
        float4 vv1 = *(const float4*)(vp + 4);
        __syncthreads();
        Ks[d8+0][kr] = kv0.x; Ks[d8+1][kr] = kv0.y;
        Ks[d8+2][kr] = kv0.z; Ks[d8+3][kr] = kv0.w;
        Ks[d8+4][kr] = kv1.x; Ks[d8+5][kr] = kv1.y;
        Ks[d8+6][kr] = kv1.z; Ks[d8+7][kr] = kv1.w;
        *(float4*)&Vs[kr][d8]     = vv0;
        *(float4*)&Vs[kr][d8 + 4] = vv1;
        __syncthreads();

        float s[4][2];
        #pragma unroll
        for (int i = 0; i < 4; i++) { s[i][0] = 0.f; s[i][1] = 0.f; }
        #pragma unroll 16
        for (int d = 0; d < 64; d++) {
            float4 qv = *(const float4*)&Qs[d][ty << 2];
            float2 kv = *(const float2*)&Ks[d][tx << 1];
            s[0][0] += qv.x * kv.x; s[0][1] += qv.x * kv.y;
            s[1][0] += qv.y * kv.x; s[1][1] += qv.y * kv.y;
            s[2][0] += qv.z * kv.x; s[2][1] += qv.z * kv.y;
            s[3][0] += qv.w * kv.x; s[3][1] += qv.w * kv.y;
        }

        #pragma unroll
        for (int i = 0; i < 4; i++) {
            float a0 = s[i][0] * 0.125f;
            float a1 = s[i][1] * 0.125f;
            float rm = fmaxf(a0, a1);
            #pragma unroll
            for (int msk = 1; msk < 16; msk <<= 1)
                rm = fmaxf(rm, __shfl_xor_sync(0xffffffffu, rm, msk));
            float mnew  = fmaxf(m_i[i], rm);
            float p0    = __expf(a0 - mnew);
            float p1    = __expf(a1 - mnew);
            float alpha = __expf(m_i[i] - mnew);
            m_i[i] = mnew;
            float rs = p0 + p1;
            #pragma unroll
            for (int msk = 1; msk < 16; msk <<= 1)
                rs += __shfl_xor_sync(0xffffffffu, rs, msk);
            l_i[i] = l_i[i] * alpha + rs;
            o[i][0] *= alpha; o[i][1] *= alpha; o[i][2] *= alpha; o[i][3] *= alpha;
            Ps[(tx << 1) + 0][(ty << 2) + i] = p0;
            Ps[(tx << 1) + 1][(ty << 2) + i] = p1;
        }
        __syncthreads();

        #pragma unroll 8
        for (int kk = 0; kk < 32; kk++) {
            float4 pv = *(const float4*)&Ps[kk][ty << 2];
            float4 vv = *(const float4*)&Vs[kk][tx << 2];
            o[0][0] += pv.x * vv.x; o[0][1] += pv.x * vv.y;
            o[0][2] += pv.x * vv.z; o[0][3] += pv.x * vv.w;
            o[1][0] += pv.y * vv.x; o[1][1] += pv.y * vv.y;
            o[1][2] += pv.y * vv.z; o[1][3] += pv.y * vv.w;
            o[2][0] += pv.z * vv.x; o[2][1] += pv.z * vv.y;
            o[2][2] += pv.z * vv.z; o[2][3] += pv.z * vv.w;
            o[3][0] += pv.w * vv.x; o[3][1] += pv.w * vv.y;
            o[3][2] += pv.w * vv.z; o[3][3] += pv.w * vv.w;
        }
    }

    #pragma unroll
    for (int i = 0; i < 4; i++) {
        float inv = 1.0f / l_i[i];
        float4 ov = make_float4(o[i][0] * inv, o[i][1] * inv,
                                o[i][2] * inv, o[i][3] * inv);
        int q = qt * 64 + (ty << 2) + i;
        size_t idx = ((size_t)(b * S_ + q)) * DM + h * DK + (tx << 2);
        *(float4*)(outA + idx) = ov;
    }
}

// ---------------------------------------------------------------------------
extern "C" void kernel_launch(void* const* d_in, const int* in_sizes, int n_in,
                              void* d_out, int out_size)
{
    const float* q  = (const float*)d_in[0];
    const float* k  = (const float*)d_in[1];
    const float* v  = (const float*)d_in[2];
    const float* Wq = (const float*)d_in[3];
    const float* bq = (const float*)d_in[4];
    const float* Wk = (const float*)d_in[5];
    const float* bk = (const float*)d_in[6];
    const float* Wv = (const float*)d_in[7];
    const float* bv = (const float*)d_in[8];
    const float* Wo = (const float*)d_in[9];
    const float* bo = (const float*)d_in[10];
    float* out = (float*)d_out;

    float *gQ, *gK, *gV, *gA;
    cudaGetSymbolAddress((void**)&gQ, g_Q);
    cudaGetSymbolAddress((void**)&gK, g_K);
    cudaGetSymbolAddress((void**)&gV, g_V);
    cudaGetSymbolAddress((void**)&gA, g_attn);

    dim3 gg(DM / 128, M_ / 128);   // (8, 64)
    gemm_mma<<<gg, 256>>>(q, Wq, bq, gQ, 1);
    gemm_mma<<<gg, 256>>>(k, Wk, bk, gK, 1);
    gemm_mma<<<gg, 256>>>(v, Wv, bv, gV, 1);
    attn_kernel<<<dim3(S_ / 64, H_, B_), 256>>>(gQ, gK, gV, gA);
    gemm_mma<<<gg, 256>>>(gA, Wo, bo, out, 0);
}

// round 4
// speedup vs baseline: 2.4875x; 2.0254x over previous
#include <cuda_runtime.h>
#include <cuda_bf16.h>
#include <math_constants.h>
#include <cstdint>

#define B_  4
#define H_  16
#define S_  2048
#define DM  1024
#define DK  64
#define M_  (B_*S_)

// ---------------- scratch (device globals; no allocation allowed) ----------
__device__ float g_Q[M_*DM];
__device__ float g_K[M_*DM];
__device__ float g_V[M_*DM];
__device__ float g_attn[M_*DM];

__device__ __forceinline__ uint32_t smem_u32(const void* p) {
    uint32_t a;
    asm("{ .reg .u64 t; cvta.to.shared.u64 t, %1; cvt.u32.u64 %0, t; }"
        : "=r"(a) : "l"(p));
    return a;
}

__device__ __forceinline__ void ldsm_x4(uint32_t r[4], uint32_t addr) {
    asm volatile("ldmatrix.sync.aligned.m8n8.x4.shared.b16 {%0,%1,%2,%3}, [%4];"
        : "=r"(r[0]), "=r"(r[1]), "=r"(r[2]), "=r"(r[3]) : "r"(addr));
}
__device__ __forceinline__ void ldsm_x2(uint32_t r[2], uint32_t addr) {
    asm volatile("ldmatrix.sync.aligned.m8n8.x2.shared.b16 {%0,%1}, [%2];"
        : "=r"(r[0]), "=r"(r[1]) : "r"(addr));
}
__device__ __forceinline__ void ldsm_x2t(uint32_t r[2], uint32_t addr) {
    asm volatile("ldmatrix.sync.aligned.m8n8.x2.trans.shared.b16 {%0,%1}, [%2];"
        : "=r"(r[0]), "=r"(r[1]) : "r"(addr));
}
__device__ __forceinline__ void mma16816(float d[4], const uint32_t a[4],
                                         const uint32_t b[2]) {
    asm volatile(
        "mma.sync.aligned.m16n8k16.row.col.f32.bf16.bf16.f32 "
        "{%0,%1,%2,%3}, {%4,%5,%6,%7}, {%8,%9}, {%0,%1,%2,%3};"
        : "+f"(d[0]), "+f"(d[1]), "+f"(d[2]), "+f"(d[3])
        : "r"(a[0]), "r"(a[1]), "r"(a[2]), "r"(a[3]), "r"(b[0]), "r"(b[1]));
}

__device__ __forceinline__ uint32_t pk_bf2(float x, float y) {
    __nv_bfloat162 h = __floats2bfloat162_rn(x, y);
    return *reinterpret_cast<uint32_t*>(&h);
}

// Split 8 fp32 (two float4) into hi/lo bf16x8 (uint4 each)
__device__ __forceinline__ void split8(float4 v0, float4 v1,
                                       uint4& hi, uint4& lo) {
    float h[8], f[8] = {v0.x, v0.y, v0.z, v0.w, v1.x, v1.y, v1.z, v1.w};
    float l[8];
    #pragma unroll
    for (int i = 0; i < 8; i++) {
        __nv_bfloat16 hb = __float2bfloat16_rn(f[i]);
        h[i] = __bfloat162float(hb);
        l[i] = f[i] - h[i];
    }
    hi = make_uint4(pk_bf2(h[0],h[1]), pk_bf2(h[2],h[3]),
                    pk_bf2(h[4],h[5]), pk_bf2(h[6],h[7]));
    lo = make_uint4(pk_bf2(l[0],l[1]), pk_bf2(l[2],l[3]),
                    pk_bf2(l[4],l[5]), pk_bf2(l[6],l[7]));
}

// Split a pair to packed bf16 hi and lo
__device__ __forceinline__ void split2(float x, float y,
                                       uint32_t& hi, uint32_t& lo) {
    __nv_bfloat162 h2 = __floats2bfloat162_rn(x, y);
    float2 hf = __bfloat1622float2(h2);
    __nv_bfloat162 l2 = __floats2bfloat162_rn(x - hf.x, y - hf.y);
    hi = *reinterpret_cast<uint32_t*>(&h2);
    lo = *reinterpret_cast<uint32_t*>(&l2);
}

// Fast exp2 on FMA pipe (no MUFU). x <= 0 expected; abs err ~2e-6 on p<=1.
__device__ __forceinline__ float exp2fast(float x) {
    x = fmaxf(x, -126.0f);
    float z = x + 12582912.0f;                 // 2^23 + 2^22: RN to integer
    int   k = __float_as_int(z) - 0x4B400000;  // integer part
    float f = x - (z - 12582912.0f);           // f in [-0.5, 0.5]
    float p = fmaf(0.00133336f, f, 0.00961813f);
    p = fmaf(p, f, 0.05550411f);
    p = fmaf(p, f, 0.24022651f);
    p = fmaf(p, f, 0.69314718f);
    p = fmaf(p, f, 1.0f);
    return __int_as_float(__float_as_int(p) + (k << 23));
}

// ---------------------------------------------------------------------------
// Tensor-core GEMM (unchanged from R3, verified): out = A*W^T + bias
// ---------------------------------------------------------------------------
#define TSTR   80
#define TILEB  (128*TSTR)
#define A_HI   0
#define A_LO   TILEB
#define W_HI   (2*TILEB)
#define W_LO   (3*TILEB)

__global__ __launch_bounds__(256)
void gemm_mma(const float* __restrict__ A, const float* __restrict__ W,
              const float* __restrict__ bias, float* __restrict__ out,
              int split_heads)
{
    __shared__ __align__(16) char sm[4*TILEB];
    const uint32_t sb = smem_u32(sm);

    const int tid = threadIdx.x;
    const int m0  = blockIdx.y << 7;
    const int n0  = blockIdx.x << 7;
    const int warp = tid >> 5;
    const int lane = tid & 31;
    const int wm = (warp >> 2) * 64;
    const int wn = (warp & 3) * 32;

    const uint32_t arow = (lane & 15) * TSTR + (lane >> 4) * 16;
    const uint32_t brow = (lane & 7) * TSTR + ((lane >> 3) & 1) * 16;

    const int lrow = tid >> 1;
    const int lcg  = (tid & 1) * 16;
    const float* Ag = A + (size_t)(m0 + lrow) * DM + lcg;
    const float* Wg = W + (size_t)(n0 + lrow) * DM + lcg;
    char* smArow = sm + lrow * TSTR + lcg * 2;
    char* smWrow = smArow;

    float acc[4][4][4];
    #pragma unroll
    for (int i = 0; i < 4; i++)
        #pragma unroll
        for (int j = 0; j < 4; j++)
            #pragma unroll
            for (int r = 0; r < 4; r++) acc[i][j][r] = 0.f;

    float4 ra0 = *(const float4*)(Ag);      float4 ra1 = *(const float4*)(Ag + 4);
    float4 ra2 = *(const float4*)(Ag + 8);  float4 ra3 = *(const float4*)(Ag + 12);
    float4 rw0 = *(const float4*)(Wg);      float4 rw1 = *(const float4*)(Wg + 4);
    float4 rw2 = *(const float4*)(Wg + 8);  float4 rw3 = *(const float4*)(Wg + 12);

    for (int c = 0; c < DM / 32; ++c) {
        __syncthreads();
        uint4 hi, lo;
        split8(ra0, ra1, hi, lo);
        *(uint4*)(smArow + A_HI)      = hi;  *(uint4*)(smArow + A_LO)      = lo;
        split8(ra2, ra3, hi, lo);
        *(uint4*)(smArow + A_HI + 16) = hi;  *(uint4*)(smArow + A_LO + 16) = lo;
        split8(rw0, rw1, hi, lo);
        *(uint4*)(smWrow + W_HI)      = hi;  *(uint4*)(smWrow + W_LO)      = lo;
        split8(rw2, rw3, hi, lo);
        *(uint4*)(smWrow + W_HI + 16) = hi;  *(uint4*)(smWrow + W_LO + 16) = lo;
        __syncthreads();

        if (c < DM / 32 - 1) {
            const float* An = Ag + (c + 1) * 32;
            const float* Wn = Wg + (c + 1) * 32;
            ra0 = *(const float4*)(An);      ra1 = *(const float4*)(An + 4);
            ra2 = *(const float4*)(An + 8);  ra3 = *(const float4*)(An + 12);
            rw0 = *(const float4*)(Wn);      rw1 = *(const float4*)(Wn + 4);
            rw2 = *(const float4*)(Wn + 8);  rw3 = *(const float4*)(Wn + 12);
        }

        #pragma unroll
        for (int pass = 0; pass < 3; ++pass) {
            const uint32_t aoff = (pass == 1) ? A_LO : A_HI;
            const uint32_t boff = (pass == 2) ? W_LO : W_HI;
            #pragma unroll
            for (int ks = 0; ks < 2; ++ks) {
                uint32_t af[4][4], bf[4][2];
                #pragma unroll
                for (int mt = 0; mt < 4; ++mt)
                    ldsm_x4(af[mt], sb + aoff + (wm + mt*16) * TSTR
                                        + ks * 32 + arow);
                #pragma unroll
                for (int nt = 0; nt < 4; ++nt)
                    ldsm_x2(bf[nt], sb + boff + (wn + nt*8) * TSTR
                                        + ks * 32 + brow);
                #pragma unroll
                for (int mt = 0; mt < 4; ++mt)
                    #pragma unroll
                    for (int nt = 0; nt < 4; ++nt)
                        mma16816(acc[mt][nt], af[mt], bf[nt]);
            }
        }
    }

    #pragma unroll
    for (int mt = 0; mt < 4; ++mt) {
        #pragma unroll
        for (int nt = 0; nt < 4; ++nt) {
            const int col = n0 + wn + nt*8 + (lane & 3) * 2;
            const float2 bv = *(const float2*)(bias + col);
            #pragma unroll
            for (int half = 0; half < 2; ++half) {
                const int row = m0 + wm + mt*16 + (lane >> 2) + half * 8;
                float2 o2 = make_float2(acc[mt][nt][2*half]   + bv.x,
                                        acc[mt][nt][2*half+1] + bv.y);
                size_t idx;
                if (split_heads) {
                    const int head = col >> 6;
                    const int bi = row >> 11, si = row & (S_ - 1);
                    idx = (((size_t)(bi * H_ + head)) * S_ + si) * DK + (col & 63);
                } else {
                    idx = (size_t)row * DM + col;
                }
                *(float2*)(out + idx) = o2;
            }
        }
    }
}

// ---------------------------------------------------------------------------
// Tensor-core flash attention.
// CTA: 128 q-rows of one (b,h); 8 warps x 16 q-rows; key tiles of 64.
// Q pre-scaled by 0.125*log2(e) -> softmax in exp2 domain (FMA-pipe exp2).
// Q/K and P/V both hi/lo bf16 split (3-pass MMA each).
// smem rows strided 144B -> conflict-free ldmatrix.
// ---------------------------------------------------------------------------
#define ASTR   144
#define A_QHI  0
#define A_QLO  18432
#define A_KHI  36864
#define A_KLO  46080
#define A_VHI  55296
#define A_VLO  64512
#define ATTN_SMEM 73728

extern __shared__ char dynsm[];

__global__ __launch_bounds__(256, 1)
void attn_mma(const float* __restrict__ Qh, const float* __restrict__ Kh,
              const float* __restrict__ Vh, float* __restrict__ outA)
{
    const uint32_t sb = smem_u32(dynsm);
    const int tid = threadIdx.x;
    const int lane = tid & 31;
    const int warp = tid >> 5;
    const int qt = blockIdx.x, h = blockIdx.y, b = blockIdx.z;

    const size_t bh = (size_t)(b * H_ + h) * S_ * DK;
    const float* Qb = Qh + bh + (size_t)qt * 128 * DK;
    const float* Kb = Kh + bh;
    const float* Vb = Vh + bh;

    // ---- Q: load, scale by 0.125*log2(e), hi/lo split, store to smem ----
    {
        const int row = tid >> 1;
        const int c0  = (tid & 1) * 32;
        const float* g = Qb + row * DK + c0;
        char* s = dynsm + row * ASTR + c0 * 2;
        const float sc = 0.1803368801f;     // 0.125 * log2(e)
        #pragma unroll
        for (int j = 0; j < 4; j++) {
            float4 v0 = *(const float4*)(g + j*8);
            float4 v1 = *(const float4*)(g + j*8 + 4);
            v0.x *= sc; v0.y *= sc; v0.z *= sc; v0.w *= sc;
            v1.x *= sc; v1.y *= sc; v1.z *= sc; v1.w *= sc;
            uint4 hi, lo; split8(v0, v1, hi, lo);
            *(uint4*)(s + A_QHI + j*16) = hi;
            *(uint4*)(s + A_QLO + j*16) = lo;
        }
    }

    // softmax state (2 rows per lane: r0 = lane>>2, r0+8)
    float m0 = -1e30f, m1 = -1e30f, l0 = 0.f, l1 = 0.f;
    float o[8][4];
    #pragma unroll
    for (int nf = 0; nf < 8; nf++)
        #pragma unroll
        for (int r = 0; r < 4; r++) o[nf][r] = 0.f;

    // K/V loader mapping: row = tid>>2 (0..63), 16 floats at (tid&3)*16
    const int krow = tid >> 2;
    const int kcg  = (tid & 3) * 16;
    char* kvs = dynsm + krow * ASTR + kcg * 2;

    // prologue: prefetch tile 0
    float4 kf[4], vf[4];
    {
        const float* kg = Kb + (size_t)krow * DK + kcg;
        const float* vg = Vb + (size_t)krow * DK + kcg;
        #pragma unroll
        for (int j = 0; j < 4; j++) {
            kf[j] = *(const float4*)(kg + j*4);
            vf[j] = *(const float4*)(vg + j*4);
        }
    }

    const uint32_t qrow = (warp * 16 + (lane & 15)) * ASTR + (lane >> 4) * 16;
    const uint32_t kbrow = (lane & 7) * ASTR + ((lane >> 3) & 1) * 16;
    const uint32_t vbrow = (lane & 15) * ASTR;

    for (int kt = 0; kt < S_ / 64; ++kt) {
        __syncthreads();
        {
            uint4 hi, lo;
            split8(kf[0], kf[1], hi, lo);
            *(uint4*)(kvs + A_KHI)      = hi;  *(uint4*)(kvs + A_KLO)      = lo;
            split8(kf[2], kf[3], hi, lo);
            *(uint4*)(kvs + A_KHI + 16) = hi;  *(uint4*)(kvs + A_KLO + 16) = lo;
            split8(vf[0], vf[1], hi, lo);
            *(uint4*)(kvs + A_VHI)      = hi;  *(uint4*)(kvs + A_VLO)      = lo;
            split8(vf[2], vf[3], hi, lo);
            *(uint4*)(kvs + A_VHI + 16) = hi;  *(uint4*)(kvs + A_VLO + 16) = lo;
        }
        __syncthreads();

        if (kt < S_ / 64 - 1) {
            const float* kg = Kb + (size_t)((kt+1)*64 + krow) * DK + kcg;
            const float* vg = Vb + (size_t)((kt+1)*64 + krow) * DK + kcg;
            #pragma unroll
            for (int j = 0; j < 4; j++) {
                kf[j] = *(const float4*)(kg + j*4);
                vf[j] = *(const float4*)(vg + j*4);
            }
        }

        // ---- scores: S[16q x 64k] = Q * K^T (3-pass hi/lo) ----
        float sacc[8][4];
        #pragma unroll
        for (int nf = 0; nf < 8; nf++)
            #pragma unroll
            for (int r = 0; r < 4; r++) sacc[nf][r] = 0.f;

        #pragma unroll
        for (int ks = 0; ks < 4; ++ks) {
            uint32_t ah[4], al[4];
            ldsm_x4(ah, sb + A_QHI + qrow + ks * 32);
            ldsm_x4(al, sb + A_QLO + qrow + ks * 32);
            #pragma unroll
            for (int nf = 0; nf < 8; ++nf) {
                uint32_t bh2[2], bl2[2];
                const uint32_t ko = nf * 8 * ASTR + ks * 32 + kbrow;
                ldsm_x2(bh2, sb + A_KHI + ko);
                ldsm_x2(bl2, sb + A_KLO + ko);
                mma16816(sacc[nf], ah, bh2);
                mma16816(sacc[nf], al, bh2);
                mma16816(sacc[nf], ah, bl2);
            }
        }

        // ---- online softmax (exp2 domain) ----
        float rm0 = -1e30f, rm1 = -1e30f;
        #pragma unroll
        for (int nf = 0; nf < 8; nf++) {
            rm0 = fmaxf(rm0, fmaxf(sacc[nf][0], sacc[nf][1]));
            rm1 = fmaxf(rm1, fmaxf(sacc[nf][2], sacc[nf][3]));
        }
        rm0 = fmaxf(rm0, __shfl_xor_sync(0xffffffffu, rm0, 1));
        rm0 = fmaxf(rm0, __shfl_xor_sync(0xffffffffu, rm0, 2));
        rm1 = fmaxf(rm1, __shfl_xor_sync(0xffffffffu, rm1, 1));
        rm1 = fmaxf(rm1, __shfl_xor_sync(0xffffffffu, rm1, 2));
        const float mn0 = fmaxf(m0, rm0), mn1 = fmaxf(m1, rm1);
        const float alpha0 = exp2fast(m0 - mn0);
        const float alpha1 = exp2fast(m1 - mn1);
        m0 = mn0; m1 = mn1;

        uint32_t pahi[4][4], palo[4][4];
        float rs0 = 0.f, rs1 = 0.f;
        #pragma unroll
        for (int nf = 0; nf < 8; nf++) {
            float p0 = exp2fast(sacc[nf][0] - mn0);
            float p1 = exp2fast(sacc[nf][1] - mn0);
            float p2 = exp2fast(sacc[nf][2] - mn1);
            float p3 = exp2fast(sacc[nf][3] - mn1);
            rs0 += p0 + p1;
            rs1 += p2 + p3;
            const int ks = nf >> 1, hf = (nf & 1) * 2;
            split2(p0, p1, pahi[ks][hf],     palo[ks][hf]);
            split2(p2, p3, pahi[ks][hf + 1], palo[ks][hf + 1]);
        }
        rs0 += __shfl_xor_sync(0xffffffffu, rs0, 1);
        rs0 += __shfl_xor_sync(0xffffffffu, rs0, 2);
        rs1 += __shfl_xor_sync(0xffffffffu, rs1, 1);
        rs1 += __shfl_xor_sync(0xffffffffu, rs1, 2);
        l0 = l0 * alpha0 + rs0;
        l1 = l1 * alpha1 + rs1;

        #pragma unroll
        for (int nf = 0; nf < 8; nf++) {
            o[nf][0] *= alpha0; o[nf][1] *= alpha0;
            o[nf][2] *= alpha1; o[nf][3] *= alpha1;
        }

        // ---- O += P * V (3-pass hi/lo); B frags via ldmatrix.trans ----
        #pragma unroll
        for (int ks = 0; ks < 4; ++ks) {
            #pragma unroll
            for (int nf = 0; nf < 8; ++nf) {
                uint32_t bh2[2], bl2[2];
                const uint32_t vo = ks * 16 * ASTR + vbrow + nf * 16;
                ldsm_x2t(bh2, sb + A_VHI + vo);
                ldsm_x2t(bl2, sb + A_VLO + vo);
                mma16816(o[nf], pahi[ks], bh2);
                mma16816(o[nf], palo[ks], bh2);
                mma16816(o[nf], pahi[ks], bl2);
            }
        }
    }

    // ---- epilogue: normalize and store merged [B, S, H*Dk] ----
    const float i0 = 1.0f / l0;
    const float i1 = 1.0f / l1;
    const int r0 = qt * 128 + warp * 16 + (lane >> 2);
    #pragma unroll
    for (int nf = 0; nf < 8; nf++) {
        const int col = h * 64 + nf * 8 + (lane & 3) * 2;
        *(float2*)(outA + (size_t)(b * S_ + r0) * DM + col) =
            make_float2(o[nf][0] * i0, o[nf][1] * i0);
        *(float2*)(outA + (size_t)(b * S_ + r0 + 8) * DM + col) =
            make_float2(o[nf][2] * i1, o[nf][3] * i1);
    }
}

// ---------------------------------------------------------------------------
extern "C" void kernel_launch(void* const* d_in, const int* in_sizes, int n_in,
                              void* d_out, int out_size)
{
    const float* q  = (const float*)d_in[0];
    const float* k  = (const float*)d_in[1];
    const float* v  = (const float*)d_in[2];
    const float* Wq = (const float*)d_in[3];
    const float* bq = (const float*)d_in[4];
    const float* Wk = (const float*)d_in[5];
    const float* bk = (const float*)d_in[6];
    const float* Wv = (const float*)d_in[7];
    const float* bv = (const float*)d_in[8];
    const float* Wo = (const float*)d_in[9];
    const float* bo = (const float*)d_in[10];
    float* out = (float*)d_out;

    float *gQ, *gK, *gV, *gA;
    cudaGetSymbolAddress((void**)&gQ, g_Q);
    cudaGetSymbolAddress((void**)&gK, g_K);
    cudaGetSymbolAddress((void**)&gV, g_V);
    cudaGetSymbolAddress((void**)&gA, g_attn);

    cudaFuncSetAttribute(attn_mma,
        cudaFuncAttributeMaxDynamicSharedMemorySize, ATTN_SMEM);

    dim3 gg(DM / 128, M_ / 128);   // (8, 64)
    gemm_mma<<<gg, 256>>>(q, Wq, bq, gQ, 1);
    gemm_mma<<<gg, 256>>>(k, Wk, bk, gK, 1);
    gemm_mma<<<gg, 256>>>(v, Wv, bv, gV, 1);
    attn_mma<<<dim3(S_ / 128, H_, B_), 256, ATTN_SMEM>>>(gQ, gK, gV, gA);
    gemm_mma<<<gg, 256>>>(gA, Wo, bo, out, 0);
}